// round 2
// baseline (speedup 1.0000x reference)
#include <cuda_runtime.h>
#include <cstdint>

#define B_    32
#define S_    2048
#define DH    512
#define E2    1024
#define INDIM 1536

#define STILE 128
#define KBLK  32
#define NKB   (E2 / KBLK)     // 32 k-blocks per d-chunk
#define LDA   36              // padded row stride (floats): conflict-free frags, 16B aligned
#define TILE_FLOATS (STILE * LDA)
#define SCH   256             // context s-chunk

// scratch (no cudaMalloc allowed)
__device__ int   d_len[B_];
__device__ float d_g[B_ * DH];
__device__ float d_scores[B_ * S_];
__device__ float d_energy[B_ * S_];

__device__ __forceinline__ float fast_tanh(float x) {
    float y;
    asm("tanh.approx.f32 %0, %1;" : "=f"(y) : "f"(x));
    return y;
}

__device__ __forceinline__ unsigned tf32r(float x) {
    unsigned y;
    asm("cvt.rna.tf32.f32 %0, %1;" : "=r"(y) : "f"(x));
    return y;
}

__device__ __forceinline__ void cp16(float* dst_smem, const float* src_gmem) {
    unsigned int ds = (unsigned int)__cvta_generic_to_shared(dst_smem);
    asm volatile("cp.async.cg.shared.global [%0], [%1], 16;\n" :: "r"(ds), "l"(src_gmem));
}

// ---------------- Kernel 0: lengths dtype detection + widen to int ----------------
// Reference declares int64, but jax without x64 silently yields int32. Inspect only
// the first 128 bytes (valid under both dtypes for 32 elements): int64 layout has all
// odd 32-bit words == 0 (values <= 2048); int32 layout has them all >= 1.
__global__ void k_lengths(const void* __restrict__ lens) {
    const int* w = (const int*)lens;
    bool is64 = true;
#pragma unroll
    for (int i = 1; i < 32; i += 2)
        if (w[i] != 0) { is64 = false; break; }
    int t = threadIdx.x;  // 32 threads
    if (is64) d_len[t] = (int)((const long long*)lens)[t];
    else      d_len[t] = w[t];
}

// ---------------- Kernel 1: g[b,d] = attn_b[d] + sum_j hidden[b,j] * attn_w[d, j] ----------------
__global__ void k_hidden(const float* __restrict__ hidden,
                         const float* __restrict__ attn_w,
                         const float* __restrict__ attn_b) {
    int b = blockIdx.x;
    int d = threadIdx.x;  // 512 threads
    __shared__ float hs[DH];
    hs[d] = hidden[b * DH + d];
    __syncthreads();
    const float4* wr = (const float4*)(attn_w + (size_t)d * INDIM);
    float acc = attn_b[d];
#pragma unroll 4
    for (int j4 = 0; j4 < DH / 4; j4++) {
        float4 w = wr[j4];
        const float* h4 = &hs[j4 * 4];
        acc += w.x * h4[0] + w.y * h4[1] + w.z * h4[2] + w.w * h4[3];
    }
    d_g[b * DH + d] = acc;
}

// ---------------- Kernel 2: scores[b,s] = v_b + sum_d v[d] * tanh( enc@W_enc^T + g ) ----------------
// tf32 mma.sync m16n8k8. Block: 256 threads (8 warps: 4 in M x 2 in N).
// Per block: 128 s-rows, loop 4 d-chunks of 128; K=1024 double-buffered in blocks of 32.
__global__ void __launch_bounds__(256, 2) k_scores(
    const float* __restrict__ enc, const float* __restrict__ attn_w,
    const float* __restrict__ v_w, const float* __restrict__ v_b)
{
    extern __shared__ float sm[];
    float* As  = sm;                          // 2 * TILE_FLOATS
    float* Bs  = sm + 2 * TILE_FLOATS;        // 2 * TILE_FLOATS
    float* gs  = sm + 4 * TILE_FLOATS;        // 128
    float* vs  = gs + 128;                    // 128
    float* ssc = vs + 128;                    // 128

    int b = blockIdx.y;
    int len = d_len[b];
    int s0 = blockIdx.x * STILE;
    if (s0 >= len) return;   // masked tile: softmax/context never read it

    int tid  = threadIdx.x;
    int warp = tid >> 5, lane = tid & 31;
    int wm = warp & 3;          // row group: wm*32
    int wn = warp >> 2;         // d group within chunk: wn*64
    int g4 = lane >> 2, tg = lane & 3;

    const float* Ag = enc + ((size_t)b * S_ + s0) * E2;

    if (tid < STILE) ssc[tid] = v_b[0];

    int lrow = tid >> 3;        // 0..31
    int lc4  = (tid & 7) * 4;   // 0,4,...,28

    for (int chunk = 0; chunk < 4; chunk++) {
        if (tid < 128) {
            gs[tid] = d_g[b * DH + chunk * 128 + tid];
            vs[tid] = v_w[chunk * 128 + tid];
        }
        const float* Bg = attn_w + (size_t)(chunk * 128) * INDIM + DH;  // skip hidden columns

        float acc[2][8][4];
#pragma unroll
        for (int mt = 0; mt < 2; mt++)
#pragma unroll
            for (int nt = 0; nt < 8; nt++)
#pragma unroll
                for (int i = 0; i < 4; i++) acc[mt][nt][i] = 0.f;

        // prologue: k-block 0 into buffer 0
        {
#pragma unroll
            for (int p = 0; p < 4; p++) {
                int r = lrow + p * 32;
                cp16(As + r * LDA + lc4, Ag + (size_t)r * E2 + lc4);
                cp16(Bs + r * LDA + lc4, Bg + (size_t)r * INDIM + lc4);
            }
            asm volatile("cp.async.commit_group;\n");
        }

        for (int kb = 0; kb < NKB; kb++) {
            if (kb + 1 < NKB) {
                int k0 = (kb + 1) * KBLK;
                int bn = (kb + 1) & 1;
#pragma unroll
                for (int p = 0; p < 4; p++) {
                    int r = lrow + p * 32;
                    cp16(As + bn * TILE_FLOATS + r * LDA + lc4, Ag + (size_t)r * E2 + k0 + lc4);
                    cp16(Bs + bn * TILE_FLOATS + r * LDA + lc4, Bg + (size_t)r * INDIM + k0 + lc4);
                }
                asm volatile("cp.async.commit_group;\n");
                asm volatile("cp.async.wait_group 1;\n");
            } else {
                asm volatile("cp.async.wait_group 0;\n");
            }
            __syncthreads();

            const float* Ab = As + (kb & 1) * TILE_FLOATS;
            const float* Bb = Bs + (kb & 1) * TILE_FLOATS;

#pragma unroll
            for (int ks = 0; ks < 4; ks++) {
                int k = ks * 8;
                unsigned int a[2][4], bf[8][2];
#pragma unroll
                for (int mt = 0; mt < 2; mt++) {
                    const float* ap = Ab + (wm * 32 + mt * 16 + g4) * LDA + k + tg;
                    a[mt][0] = tf32r(ap[0]);
                    a[mt][1] = tf32r(ap[8 * LDA]);
                    a[mt][2] = tf32r(ap[4]);
                    a[mt][3] = tf32r(ap[8 * LDA + 4]);
                }
#pragma unroll
                for (int nt = 0; nt < 8; nt++) {
                    const float* bp = Bb + (wn * 64 + nt * 8 + g4) * LDA + k + tg;
                    bf[nt][0] = tf32r(bp[0]);
                    bf[nt][1] = tf32r(bp[4]);
                }
#pragma unroll
                for (int mt = 0; mt < 2; mt++)
#pragma unroll
                    for (int nt = 0; nt < 8; nt++) {
                        asm volatile(
                            "mma.sync.aligned.m16n8k8.row.col.f32.tf32.tf32.f32 "
                            "{%0,%1,%2,%3}, {%4,%5,%6,%7}, {%8,%9}, {%0,%1,%2,%3};\n"
                            : "+f"(acc[mt][nt][0]), "+f"(acc[mt][nt][1]),
                              "+f"(acc[mt][nt][2]), "+f"(acc[mt][nt][3])
                            : "r"(a[mt][0]), "r"(a[mt][1]), "r"(a[mt][2]), "r"(a[mt][3]),
                              "r"(bf[nt][0]), "r"(bf[nt][1]));
                    }
            }
            __syncthreads();
        }

        // epilogue: score_partial = sum_d v[d] * tanh(u + g)
#pragma unroll
        for (int mt = 0; mt < 2; mt++) {
            float p0 = 0.f, p1 = 0.f;
#pragma unroll
            for (int nt = 0; nt < 8; nt++) {
                int d0 = wn * 64 + nt * 8 + tg * 2;
                float va = vs[d0], vb2 = vs[d0 + 1];
                float ga = gs[d0], gb2 = gs[d0 + 1];
                p0 += va * fast_tanh(acc[mt][nt][0] + ga) + vb2 * fast_tanh(acc[mt][nt][1] + gb2);
                p1 += va * fast_tanh(acc[mt][nt][2] + ga) + vb2 * fast_tanh(acc[mt][nt][3] + gb2);
            }
            p0 += __shfl_xor_sync(0xffffffffu, p0, 1);
            p0 += __shfl_xor_sync(0xffffffffu, p0, 2);
            p1 += __shfl_xor_sync(0xffffffffu, p1, 1);
            p1 += __shfl_xor_sync(0xffffffffu, p1, 2);
            if (tg == 0) {
                int r = wm * 32 + mt * 16 + g4;
                atomicAdd(&ssc[r], p0);
                atomicAdd(&ssc[r + 8], p1);
            }
        }
        __syncthreads();  // protect gs/vs/ssc before next chunk
    }

    if (tid < STILE) d_scores[b * S_ + s0 + tid] = ssc[tid];
}

// ---------------- Kernel 3: masked softmax over s per batch ----------------
__global__ void k_softmax() {
    int b = blockIdx.x, tid = threadIdx.x;  // 256 threads
    int len = d_len[b];
    const float* sc = d_scores + b * S_;
    __shared__ float red[8];
    __shared__ float sM, sZ;

    float m = -3.4e38f;
    for (int s = tid; s < len; s += 256) m = fmaxf(m, sc[s]);
#pragma unroll
    for (int o = 16; o; o >>= 1) m = fmaxf(m, __shfl_xor_sync(0xffffffffu, m, o));
    if ((tid & 31) == 0) red[tid >> 5] = m;
    __syncthreads();
    if (tid == 0) {
        float mm = red[0];
        for (int i = 1; i < 8; i++) mm = fmaxf(mm, red[i]);
        sM = mm;
    }
    __syncthreads();
    float M = sM;

    float z = 0.f;
    for (int s = tid; s < len; s += 256) z += __expf(sc[s] - M);
#pragma unroll
    for (int o = 16; o; o >>= 1) z += __shfl_xor_sync(0xffffffffu, z, o);
    if ((tid & 31) == 0) red[tid >> 5] = z;
    __syncthreads();
    if (tid == 0) {
        float zz = 0.f;
        for (int i = 0; i < 8; i++) zz += red[i];
        sZ = zz;
    }
    __syncthreads();
    float inv = 1.f / sZ;
    for (int s = tid; s < len; s += 256) d_energy[b * S_ + s] = __expf(sc[s] - M) * inv;
}

// ---------------- Kernel 4: context[b,e] = sum_{s<len} energy[b,s] * enc[b,s,e] ----------------
__global__ void k_zero(float* out) {
    int i = blockIdx.x * 256 + threadIdx.x;
    if (i < B_ * E2) out[i] = 0.f;
}

__global__ void k_context(const float* __restrict__ enc,
                          float* __restrict__ out) {
    int b = blockIdx.y;
    int len = d_len[b];
    int s0 = blockIdx.x * SCH;
    if (s0 >= len) return;
    int tid = threadIdx.x;  // 256 threads, each owns 4 consecutive e (float4)
    int ns = min(SCH, len - s0);

    __shared__ float es[SCH];
    if (tid < SCH) es[tid] = (tid < ns) ? d_energy[b * S_ + s0 + tid] : 0.f;
    __syncthreads();

    const float4* e4 = (const float4*)(enc + ((size_t)b * S_ + s0) * E2);
    float4 acc = make_float4(0.f, 0.f, 0.f, 0.f);
    for (int s = 0; s < ns; s++) {
        float w = es[s];
        float4 v = e4[(size_t)s * (E2 / 4) + tid];
        acc.x += w * v.x; acc.y += w * v.y; acc.z += w * v.z; acc.w += w * v.w;
    }
    float* o = out + b * E2 + tid * 4;
    atomicAdd(o + 0, acc.x);
    atomicAdd(o + 1, acc.y);
    atomicAdd(o + 2, acc.z);
    atomicAdd(o + 3, acc.w);
}

// ---------------- launch ----------------
extern "C" void kernel_launch(void* const* d_in, const int* in_sizes, int n_in,
                              void* d_out, int out_size) {
    const float* enc          = (const float*)d_in[0];
    const float* hidden       = (const float*)d_in[1];
    const void*  lengths      = d_in[2];
    const float* attn_w       = (const float*)d_in[3];
    const float* attn_b       = (const float*)d_in[4];
    const float* v_w          = (const float*)d_in[5];
    const float* v_b          = (const float*)d_in[6];
    float* out = (float*)d_out;

    k_lengths<<<1, 32>>>(lengths);
    k_hidden<<<B_, DH>>>(hidden, attn_w, attn_b);

    size_t smem = (size_t)(4 * TILE_FLOATS + 128 + 128 + 128) * sizeof(float);
    cudaFuncSetAttribute(k_scores, cudaFuncAttributeMaxDynamicSharedMemorySize, (int)smem);
    k_scores<<<dim3(S_ / STILE, B_), 256, smem>>>(enc, attn_w, v_w, v_b);

    k_softmax<<<B_, 256>>>();

    k_zero<<<(B_ * E2 + 255) / 256, 256>>>(out);
    k_context<<<dim3(S_ / SCH, B_), 256>>>(enc, out);
}

// round 5
// speedup vs baseline: 2.1480x; 2.1480x over previous
#include <cuda_runtime.h>
#include <cuda_bf16.h>
#include <cstdint>

#define B_    32
#define S_    2048
#define DH    512
#define E2    1024
#define INDIM 1536

// ---- scores GEMM tiling (legacy bf16 mma.sync m16n8k16) ----
#define MTILE 128            // s rows per CTA
#define NTILE 128            // d cols per CTA (one of 4 n-chunks)
#define KSTG  64             // K elements per stage (bf16: 128 B rows = SW128 atom)
#define NSTG  (E2 / KSTG)    // 16 stages
#define ABYTES (MTILE * 128) // 16384 B per A stage
#define A_OFF(p) ((p) * ABYTES)
#define B_OFF(p) (2 * ABYTES + (p) * ABYTES)
#define GV_OFF   (4 * ABYTES)
#define SMEM_TOTAL (GV_OFF + 2 * NTILE * 4)

#define SCH   256            // context s-chunk
#define SWZ(off) ((off) ^ (((off) >> 3) & 0x70))

// scratch (no cudaMalloc allowed)
__device__ int   d_len[B_];
__device__ float d_g[B_ * DH];
__device__ float d_scores[B_ * S_];
__device__ float d_energy[B_ * S_];
__device__ __nv_bfloat16 d_enc_bf[(size_t)B_ * S_ * E2];   // 128 MB
__device__ __nv_bfloat16 d_w_bf[DH * E2];                  // W_enc^T rows: [d][k]

__device__ __forceinline__ float fast_tanh(float x) {
    float y; asm("tanh.approx.f32 %0, %1;" : "=f"(y) : "f"(x)); return y;
}
__device__ __forceinline__ uint32_t pack_bf2(float lo, float hi) {
    uint32_t r; asm("cvt.rn.bf16x2.f32 %0, %1, %2;" : "=r"(r) : "f"(hi), "f"(lo)); return r;
}
__device__ __forceinline__ void cp16(uint32_t dst_smem, const void* src_gmem) {
    asm volatile("cp.async.cg.shared.global [%0], [%1], 16;\n" :: "r"(dst_smem), "l"(src_gmem));
}
__device__ __forceinline__ uint32_t smem_u32(const void* p) {
    uint32_t a;
    asm("{ .reg .u64 t; cvta.to.shared.u64 t, %1; cvt.u32.u64 %0, t; }" : "=r"(a) : "l"(p));
    return a;
}
__device__ __forceinline__ void ldsm4(uint32_t& r0, uint32_t& r1, uint32_t& r2, uint32_t& r3,
                                      uint32_t addr) {
    asm volatile("ldmatrix.sync.aligned.m8n8.x4.shared.b16 {%0,%1,%2,%3}, [%4];"
                 : "=r"(r0), "=r"(r1), "=r"(r2), "=r"(r3) : "r"(addr));
}
__device__ __forceinline__ void mma_bf16(float* c, const uint32_t* a, uint32_t b0, uint32_t b1) {
    asm volatile(
        "mma.sync.aligned.m16n8k16.row.col.f32.bf16.bf16.f32 "
        "{%0,%1,%2,%3}, {%4,%5,%6,%7}, {%8,%9}, {%0,%1,%2,%3};\n"
        : "+f"(c[0]), "+f"(c[1]), "+f"(c[2]), "+f"(c[3])
        : "r"(a[0]), "r"(a[1]), "r"(a[2]), "r"(a[3]), "r"(b0), "r"(b1));
}

// ---------------- Kernel 0: lengths dtype detection + widen ----------------
// jax without x64 silently yields int32 despite the int64 annotation. First 128 bytes
// disambiguate: int64 layout has all odd 32-bit words zero (values <= 2048).
__global__ void k_lengths(const void* __restrict__ lens) {
    const int* w = (const int*)lens;
    bool is64 = true;
#pragma unroll
    for (int i = 1; i < 32; i += 2)
        if (w[i] != 0) { is64 = false; break; }
    int t = threadIdx.x;  // 32 threads
    if (is64) d_len[t] = (int)((const long long*)lens)[t];
    else      d_len[t] = w[t];
}

__global__ void k_zero_scores() {
    d_scores[blockIdx.x * 1024 + threadIdx.x] = 0.f;
}

// ---------------- prepass: fp32 -> bf16 (length-masked for enc) ----------------
__global__ void k_conv_enc(const float* __restrict__ enc) {
    int b = blockIdx.y;
    int s0 = blockIdx.x * 32;                 // 32 rows per block
    if ((s0 & ~127) >= d_len[b]) return;      // whole 128-row score tile inactive
    int tid = threadIdx.x;                    // 256
    const float2* src = (const float2*)(enc + ((size_t)b * S_ + s0) * E2);
    uint32_t* dst = (uint32_t*)(d_enc_bf + ((size_t)b * S_ + s0) * E2);
#pragma unroll 4
    for (int i = tid; i < 32 * (E2 / 2); i += 256) {
        float2 v = src[i];
        dst[i] = pack_bf2(v.x, v.y);
    }
}

__global__ void k_conv_w(const float* __restrict__ attn_w) {
    int idx = blockIdx.x * 256 + threadIdx.x;     // over DH*E2/2 pairs
    int d = idx >> 9;                              // /512
    int k2 = idx & 511;
    const float2 v = *(const float2*)(attn_w + (size_t)d * INDIM + DH + k2 * 2);
    ((uint32_t*)d_w_bf)[(size_t)d * (E2 / 2) + k2] = pack_bf2(v.x, v.y);
}

// ---------------- Kernel 1: g[b,d] = attn_b[d] + hidden[b,:]·attn_w[d,:512] ----------------
__global__ void k_hidden(const float* __restrict__ hidden,
                         const float* __restrict__ attn_w,
                         const float* __restrict__ attn_b) {
    int b = blockIdx.x;
    int d = threadIdx.x;  // 512 threads
    __shared__ float hs[DH];
    hs[d] = hidden[b * DH + d];
    __syncthreads();
    const float4* wr = (const float4*)(attn_w + (size_t)d * INDIM);
    float acc = attn_b[d];
#pragma unroll 4
    for (int j4 = 0; j4 < DH / 4; j4++) {
        float4 w = wr[j4];
        const float* h4 = &hs[j4 * 4];
        acc += w.x * h4[0] + w.y * h4[1] + w.z * h4[2] + w.w * h4[3];
    }
    d_g[b * DH + d] = acc;
}

// ---------------- Kernel 2: bf16 HMMA scores ----------------
// grid (16 s-tiles, 4 n-chunks, 32 b), 256 threads = 8 warps (4 M x 2 N).
// warp tile m32 x n64; u = enc_bf @ w_bf^T; partial score = sum_d v[d]*tanh(u+g).
__global__ void __launch_bounds__(256) k_scores(const float* __restrict__ v_w) {
    extern __shared__ char smem[];
    int b   = blockIdx.z;
    int nch = blockIdx.y;
    int s0  = blockIdx.x * MTILE;
    if (s0 >= d_len[b]) return;

    int tid = threadIdx.x;
    int w = tid >> 5, lane = tid & 31;
    int wm = w & 3, wn = w >> 2;
    uint32_t sbase = smem_u32(smem);
    float* gs = (float*)(smem + GV_OFF);
    float* vs = gs + NTILE;
    if (tid < NTILE) {
        gs[tid] = d_g[b * DH + nch * NTILE + tid];
        vs[tid] = v_w[nch * NTILE + tid];
    }

    // cp.async geometry: thread -> row tid>>1, chunks (tid&1)*4 .. +3 (16B each)
    int lrow = tid >> 1;
    int lch  = (tid & 1) * 4;
    const __nv_bfloat16* Ag = d_enc_bf + ((size_t)b * S_ + s0 + lrow) * E2 + lch * 8;
    const __nv_bfloat16* Bg = d_w_bf + ((size_t)(nch * NTILE) + lrow) * E2 + lch * 8;

#define LOAD_STAGE(stg) do {                                                  \
        int _p = (stg) & 1;                                                   \
        int _k0 = (stg) * KSTG;                                               \
        _Pragma("unroll")                                                     \
        for (int _i = 0; _i < 4; _i++) {                                      \
            uint32_t _off = SWZ(lrow * 128 + (lch + _i) * 16);                \
            cp16(sbase + A_OFF(_p) + _off, Ag + _k0 + _i * 8);                \
            cp16(sbase + B_OFF(_p) + _off, Bg + _k0 + _i * 8);                \
        }                                                                     \
        asm volatile("cp.async.commit_group;\n");                             \
    } while (0)

    // ldmatrix per-lane geometry
    int m2 = lane >> 3, r8 = lane & 7;
    int a_row = wm * 32 + r8 + (m2 & 1) * 8;
    int a_col = (m2 >> 1) * 16;                    // bytes
    int b_row = wn * 64 + r8 + (m2 >> 1) * 8;
    int b_col = (m2 & 1) * 16;

    float acc[2][8][4];
#pragma unroll
    for (int mt = 0; mt < 2; mt++)
#pragma unroll
        for (int nt = 0; nt < 8; nt++)
#pragma unroll
            for (int i = 0; i < 4; i++) acc[mt][nt][i] = 0.f;

    LOAD_STAGE(0);

    for (int kb = 0; kb < NSTG; kb++) {
        if (kb + 1 < NSTG) {
            LOAD_STAGE(kb + 1);
            asm volatile("cp.async.wait_group 1;\n");
        } else {
            asm volatile("cp.async.wait_group 0;\n");
        }
        __syncthreads();

        uint32_t SA = sbase + A_OFF(kb & 1);
        uint32_t SB = sbase + B_OFF(kb & 1);
#pragma unroll
        for (int ks = 0; ks < 4; ks++) {
            uint32_t a[2][4], bb[4][4];
#pragma unroll
            for (int mt = 0; mt < 2; mt++)
                ldsm4(a[mt][0], a[mt][1], a[mt][2], a[mt][3],
                      SA + SWZ((a_row + mt * 16) * 128 + ks * 32 + a_col));
#pragma unroll
            for (int j = 0; j < 4; j++)
                ldsm4(bb[j][0], bb[j][1], bb[j][2], bb[j][3],
                      SB + SWZ((b_row + j * 16) * 128 + ks * 32 + b_col));
#pragma unroll
            for (int mt = 0; mt < 2; mt++)
#pragma unroll
                for (int nt = 0; nt < 8; nt++) {
                    int j = nt >> 1, h = (nt & 1) * 2;
                    mma_bf16(acc[mt][nt], a[mt], bb[j][h], bb[j][h + 1]);
                }
        }
        __syncthreads();
    }

    // epilogue: partial scores
    int g4 = lane >> 2, tg = lane & 3;
#pragma unroll
    for (int mt = 0; mt < 2; mt++) {
#pragma unroll
        for (int h = 0; h < 2; h++) {
            float sum = 0.f;
#pragma unroll
            for (int nt = 0; nt < 8; nt++) {
                int c = wn * 64 + nt * 8 + tg * 2;
                sum += vs[c]     * fast_tanh(acc[mt][nt][h * 2]     + gs[c]);
                sum += vs[c + 1] * fast_tanh(acc[mt][nt][h * 2 + 1] + gs[c + 1]);
            }
            sum += __shfl_xor_sync(0xffffffffu, sum, 1);
            sum += __shfl_xor_sync(0xffffffffu, sum, 2);
            if (tg == 0) {
                int row = wm * 32 + mt * 16 + g4 + h * 8;
                atomicAdd(&d_scores[b * S_ + s0 + row], sum);
            }
        }
    }
#undef LOAD_STAGE
}

// ---------------- Kernel 3: masked softmax over s per batch ----------------
__global__ void k_softmax() {
    int b = blockIdx.x, tid = threadIdx.x;  // 1024 threads
    int len = d_len[b];
    const float* sc = d_scores + b * S_;
    __shared__ float red[32];
    __shared__ float sM, sZ;

    float m = -3.4e38f;
    for (int s = tid; s < len; s += 1024) m = fmaxf(m, sc[s]);
#pragma unroll
    for (int o = 16; o; o >>= 1) m = fmaxf(m, __shfl_xor_sync(0xffffffffu, m, o));
    if ((tid & 31) == 0) red[tid >> 5] = m;
    __syncthreads();
    if (tid == 0) {
        float mm = red[0];
        for (int i = 1; i < 32; i++) mm = fmaxf(mm, red[i]);
        sM = mm;
    }
    __syncthreads();
    float M = sM;

    float z = 0.f;
    for (int s = tid; s < len; s += 1024) z += __expf(sc[s] - M);
#pragma unroll
    for (int o = 16; o; o >>= 1) z += __shfl_xor_sync(0xffffffffu, z, o);
    if ((tid & 31) == 0) red[tid >> 5] = z;
    __syncthreads();
    if (tid == 0) {
        float zz = 0.f;
        for (int i = 0; i < 32; i++) zz += red[i];
        sZ = zz;
    }
    __syncthreads();
    float inv = 1.f / sZ;
    for (int s = tid; s < len; s += 1024) d_energy[b * S_ + s] = __expf(sc[s] - M) * inv;
}

// ---------------- Kernel 4: context (fp32 enc for accuracy) ----------------
__global__ void k_zero(float* out) {
    int i = blockIdx.x * 256 + threadIdx.x;
    if (i < B_ * E2) out[i] = 0.f;
}

__global__ void k_context(const float* __restrict__ enc,
                          float* __restrict__ out) {
    int b = blockIdx.y;
    int len = d_len[b];
    int s0 = blockIdx.x * SCH;
    if (s0 >= len) return;
    int tid = threadIdx.x;  // 256 threads, each owns 4 consecutive e
    int ns = min(SCH, len - s0);

    __shared__ float es[SCH];
    if (tid < SCH) es[tid] = (tid < ns) ? d_energy[b * S_ + s0 + tid] : 0.f;
    __syncthreads();

    const float4* e4 = (const float4*)(enc + ((size_t)b * S_ + s0) * E2);
    float4 acc = make_float4(0.f, 0.f, 0.f, 0.f);
    for (int s = 0; s < ns; s++) {
        float ww = es[s];
        float4 v = e4[(size_t)s * (E2 / 4) + tid];
        acc.x += ww * v.x; acc.y += ww * v.y; acc.z += ww * v.z; acc.w += ww * v.w;
    }
    float* o = out + b * E2 + tid * 4;
    atomicAdd(o + 0, acc.x);
    atomicAdd(o + 1, acc.y);
    atomicAdd(o + 2, acc.z);
    atomicAdd(o + 3, acc.w);
}

// ---------------- launch ----------------
extern "C" void kernel_launch(void* const* d_in, const int* in_sizes, int n_in,
                              void* d_out, int out_size) {
    const float* enc     = (const float*)d_in[0];
    const float* hidden  = (const float*)d_in[1];
    const void*  lengths = d_in[2];
    const float* attn_w  = (const float*)d_in[3];
    const float* attn_b  = (const float*)d_in[4];
    const float* v_w     = (const float*)d_in[5];
    float* out = (float*)d_out;

    k_lengths<<<1, 32>>>(lengths);
    k_zero_scores<<<B_ * S_ / 1024, 1024>>>();
    k_hidden<<<B_, DH>>>(hidden, attn_w, attn_b);
    k_conv_w<<<DH * E2 / 2 / 256, 256>>>(attn_w);
    k_conv_enc<<<dim3(S_ / 32, B_), 256>>>(enc);

    cudaFuncSetAttribute(k_scores, cudaFuncAttributeMaxDynamicSharedMemorySize, SMEM_TOTAL);
    k_scores<<<dim3(S_ / MTILE, E2 / NTILE / 2, B_), 256, SMEM_TOTAL>>>(v_w);

    k_softmax<<<B_, 1024>>>();

    k_zero<<<(B_ * E2 + 255) / 256, 256>>>(out);
    k_context<<<dim3(S_ / SCH, B_), 256>>>(enc, out);
}

// round 6
// speedup vs baseline: 2.2365x; 1.0412x over previous
#include <cuda_runtime.h>
#include <cuda_bf16.h>
#include <cstdint>

#define B_    32
#define S_    2048
#define DH    512
#define E2    1024
#define INDIM 1536

// ---- scores GEMM tiling (bf16 mma.sync m16n8k16) ----
#define MTILE 128            // s rows per CTA
#define NTILE 256            // d cols per CTA (one of 2 n-chunks)
#define KSTG  64             // K elems per stage (bf16: 128 B rows = SW128 atom)
#define NSTG  (E2 / KSTG)    // 16 stages
#define ASTG  (MTILE * 128)  // 16384 B
#define BSTG  (NTILE * 128)  // 32768 B
#define A_OFF(p) ((p) * ASTG)
#define B_OFF(p) (3 * ASTG + (p) * BSTG)
#define GV_OFF   (3 * ASTG + 3 * BSTG)
#define SMEM_TOTAL (GV_OFF + 2 * NTILE * 4)

#define SCH   256            // context s-chunk
#define SWZ(off) ((off) ^ (((off) >> 3) & 0x70))

// scratch (no cudaMalloc allowed)
__device__ int   d_len[B_];
__device__ float d_g[B_ * DH];
__device__ float d_scores[B_ * S_];
__device__ float d_energy[B_ * S_];
__device__ __nv_bfloat16 d_enc_bf[(size_t)B_ * S_ * E2];   // 128 MB
__device__ __nv_bfloat16 d_w_bf[DH * E2];                  // W_enc^T rows: [d][k]

__device__ __forceinline__ float fast_tanh(float x) {
    float y; asm("tanh.approx.f32 %0, %1;" : "=f"(y) : "f"(x)); return y;
}
__device__ __forceinline__ uint32_t pack_bf2(float lo, float hi) {
    uint32_t r; asm("cvt.rn.bf16x2.f32 %0, %1, %2;" : "=r"(r) : "f"(hi), "f"(lo)); return r;
}
__device__ __forceinline__ void cp16(uint32_t dst_smem, const void* src_gmem) {
    asm volatile("cp.async.cg.shared.global [%0], [%1], 16;\n" :: "r"(dst_smem), "l"(src_gmem));
}
__device__ __forceinline__ uint32_t smem_u32(const void* p) {
    uint32_t a;
    asm("{ .reg .u64 t; cvta.to.shared.u64 t, %1; cvt.u32.u64 %0, t; }" : "=r"(a) : "l"(p));
    return a;
}
__device__ __forceinline__ void ldsm4(uint32_t& r0, uint32_t& r1, uint32_t& r2, uint32_t& r3,
                                      uint32_t addr) {
    asm volatile("ldmatrix.sync.aligned.m8n8.x4.shared.b16 {%0,%1,%2,%3}, [%4];"
                 : "=r"(r0), "=r"(r1), "=r"(r2), "=r"(r3) : "r"(addr));
}
__device__ __forceinline__ void mma_bf16(float* c, const uint32_t* a, uint32_t b0, uint32_t b1) {
    asm volatile(
        "mma.sync.aligned.m16n8k16.row.col.f32.bf16.bf16.f32 "
        "{%0,%1,%2,%3}, {%4,%5,%6,%7}, {%8,%9}, {%0,%1,%2,%3};\n"
        : "+f"(c[0]), "+f"(c[1]), "+f"(c[2]), "+f"(c[3])
        : "r"(a[0]), "r"(a[1]), "r"(a[2]), "r"(a[3]), "r"(b0), "r"(b1));
}

// ---------------- Kernel 0: lengths dtype detection + widen ----------------
// jax without x64 silently yields int32 despite the int64 annotation. First 128 bytes
// disambiguate: int64 layout has all odd 32-bit words zero (values <= 2048).
__global__ void k_lengths(const void* __restrict__ lens) {
    const int* w = (const int*)lens;
    bool is64 = true;
#pragma unroll
    for (int i = 1; i < 32; i += 2)
        if (w[i] != 0) { is64 = false; break; }
    int t = threadIdx.x;  // 32 threads
    if (is64) d_len[t] = (int)((const long long*)lens)[t];
    else      d_len[t] = w[t];
}

// ---------------- prepass: fp32 -> bf16 (length-masked for enc) ----------------
__global__ void k_conv_enc(const float* __restrict__ enc) {
    int b = blockIdx.y;
    int s0 = blockIdx.x * 32;                 // 32 rows per block
    if ((s0 & ~127) >= d_len[b]) return;      // whole 128-row score tile inactive
    int tid = threadIdx.x;                    // 256
    const float4* src = (const float4*)(enc + ((size_t)b * S_ + s0) * E2);
    uint2* dst = (uint2*)(d_enc_bf + ((size_t)b * S_ + s0) * E2);
#pragma unroll 8
    for (int i = tid; i < 32 * (E2 / 4); i += 256) {
        float4 v = src[i];
        dst[i] = make_uint2(pack_bf2(v.x, v.y), pack_bf2(v.z, v.w));
    }
}

__global__ void k_conv_w(const float* __restrict__ attn_w) {
    int idx = blockIdx.x * 256 + threadIdx.x;     // over DH*E2/2 pairs
    int d = idx >> 9;                              // /512
    int k2 = idx & 511;
    const float2 v = *(const float2*)(attn_w + (size_t)d * INDIM + DH + k2 * 2);
    ((uint32_t*)d_w_bf)[(size_t)d * (E2 / 2) + k2] = pack_bf2(v.x, v.y);
}

// ---------------- Kernel 1: g[b,d] = attn_b[d] + hidden·attn_w[d,:512]; also zero scores ----------------
__global__ void k_hidden(const float* __restrict__ hidden,
                         const float* __restrict__ attn_w,
                         const float* __restrict__ attn_b) {
    int b = blockIdx.x;
    int d = threadIdx.x;  // 512 threads
    __shared__ float hs[DH];
    hs[d] = hidden[b * DH + d];
    // zero scores for this batch (4 per thread)
    float4* zs = (float4*)(d_scores + b * S_);
    zs[d] = make_float4(0.f, 0.f, 0.f, 0.f);
    __syncthreads();
    const float4* wr = (const float4*)(attn_w + (size_t)d * INDIM);
    float acc = attn_b[d];
#pragma unroll 4
    for (int j4 = 0; j4 < DH / 4; j4++) {
        float4 w = wr[j4];
        const float* h4 = &hs[j4 * 4];
        acc += w.x * h4[0] + w.y * h4[1] + w.z * h4[2] + w.w * h4[3];
    }
    d_g[b * DH + d] = acc;
}

// ---------------- Kernel 2: bf16 HMMA scores ----------------
// grid (16 s-tiles, 2 n-chunks, 32 b), 512 threads = 16 warps (4 M x 4 N).
// warp tile m32 x n64; u = enc_bf @ w_bf^T; partial score = sum_d v[d]*tanh(u+g).
__global__ void __launch_bounds__(512) k_scores(const float* __restrict__ v_w) {
    extern __shared__ char smem[];
    int b   = blockIdx.z;
    int nch = blockIdx.y;
    int s0  = blockIdx.x * MTILE;
    if (s0 >= d_len[b]) return;

    int tid = threadIdx.x;
    int w = tid >> 5, lane = tid & 31;
    int wm = w & 3, wn = w >> 2;                   // 4 x 4 warp grid
    uint32_t sbase = smem_u32(smem);
    float* gs = (float*)(smem + GV_OFF);
    float* vs = gs + NTILE;
    if (tid < NTILE) {
        gs[tid] = d_g[b * DH + nch * NTILE + tid];
        vs[tid] = v_w[nch * NTILE + tid];
    }

    // cp.async geometry over 16B chunks: A stage 1024 chunks, B stage 2048 chunks
    const char* Agp = (const char*)(d_enc_bf + ((size_t)b * S_ + s0) * E2);
    const char* Bgp = (const char*)(d_w_bf + (size_t)(nch * NTILE) * E2);

#define LOAD_STAGE(stg) do {                                                   \
        int _p = (stg) % 3;                                                    \
        int _k0 = (stg) * 128;  /* bytes into each 2048-B row */               \
        _Pragma("unroll")                                                      \
        for (int _i = 0; _i < 2; _i++) {                                       \
            int _c = tid + _i * 512;                                           \
            int _r = _c >> 3, _cc = (_c & 7) * 16;                             \
            cp16(sbase + A_OFF(_p) + SWZ(_r * 128 + _cc),                      \
                 Agp + (size_t)_r * 2048 + _k0 + _cc);                         \
        }                                                                      \
        _Pragma("unroll")                                                      \
        for (int _i = 0; _i < 4; _i++) {                                       \
            int _c = tid + _i * 512;                                           \
            int _r = _c >> 3, _cc = (_c & 7) * 16;                             \
            cp16(sbase + B_OFF(_p) + SWZ(_r * 128 + _cc),                      \
                 Bgp + (size_t)_r * 2048 + _k0 + _cc);                         \
        }                                                                      \
        asm volatile("cp.async.commit_group;\n");                              \
    } while (0)

    // ldmatrix per-lane geometry
    int m2 = lane >> 3, r8 = lane & 7;
    int a_row = wm * 32 + r8 + (m2 & 1) * 8;
    int a_col = (m2 >> 1) * 16;                    // bytes
    int b_row = wn * 64 + r8 + (m2 >> 1) * 8;
    int b_col = (m2 & 1) * 16;

    float acc[2][8][4];
#pragma unroll
    for (int mt = 0; mt < 2; mt++)
#pragma unroll
        for (int nt = 0; nt < 8; nt++)
#pragma unroll
            for (int i = 0; i < 4; i++) acc[mt][nt][i] = 0.f;

    LOAD_STAGE(0);
    LOAD_STAGE(1);

    for (int kb = 0; kb < NSTG; kb++) {
        if (kb + 2 < NSTG) {
            LOAD_STAGE(kb + 2);
            asm volatile("cp.async.wait_group 2;\n");
        } else if (kb + 2 == NSTG) {
            asm volatile("cp.async.wait_group 1;\n");
        } else {
            asm volatile("cp.async.wait_group 0;\n");
        }
        __syncthreads();

        uint32_t SA = sbase + A_OFF(kb % 3);
        uint32_t SB = sbase + B_OFF(kb % 3);
#pragma unroll
        for (int ks = 0; ks < 4; ks++) {
            uint32_t a[2][4], bb[4][4];
#pragma unroll
            for (int mt = 0; mt < 2; mt++)
                ldsm4(a[mt][0], a[mt][1], a[mt][2], a[mt][3],
                      SA + SWZ((a_row + mt * 16) * 128 + ks * 32 + a_col));
#pragma unroll
            for (int j = 0; j < 4; j++)
                ldsm4(bb[j][0], bb[j][1], bb[j][2], bb[j][3],
                      SB + SWZ((b_row + j * 16) * 128 + ks * 32 + b_col));
#pragma unroll
            for (int mt = 0; mt < 2; mt++)
#pragma unroll
                for (int nt = 0; nt < 8; nt++) {
                    int j = nt >> 1, h = (nt & 1) * 2;
                    mma_bf16(acc[mt][nt], a[mt], bb[j][h], bb[j][h + 1]);
                }
        }
        __syncthreads();
    }

    // epilogue: partial scores = sum_d v[d]*tanh(u+g)
    int g4 = lane >> 2, tg = lane & 3;
#pragma unroll
    for (int mt = 0; mt < 2; mt++) {
#pragma unroll
        for (int h = 0; h < 2; h++) {
            float sum = 0.f;
#pragma unroll
            for (int nt = 0; nt < 8; nt++) {
                int c = wn * 64 + nt * 8 + tg * 2;
                sum += vs[c]     * fast_tanh(acc[mt][nt][h * 2]     + gs[c]);
                sum += vs[c + 1] * fast_tanh(acc[mt][nt][h * 2 + 1] + gs[c + 1]);
            }
            sum += __shfl_xor_sync(0xffffffffu, sum, 1);
            sum += __shfl_xor_sync(0xffffffffu, sum, 2);
            if (tg == 0) {
                int row = wm * 32 + mt * 16 + g4 + h * 8;
                atomicAdd(&d_scores[b * S_ + s0 + row], sum);
            }
        }
    }
#undef LOAD_STAGE
}

// ---------------- Kernel 3: masked softmax over s per batch ----------------
__global__ void k_softmax() {
    int b = blockIdx.x, tid = threadIdx.x;  // 1024 threads
    int len = d_len[b];
    const float* sc = d_scores + b * S_;
    __shared__ float red[32];
    __shared__ float sM, sZ;

    float m = -3.4e38f;
    for (int s = tid; s < len; s += 1024) m = fmaxf(m, sc[s]);
#pragma unroll
    for (int o = 16; o; o >>= 1) m = fmaxf(m, __shfl_xor_sync(0xffffffffu, m, o));
    if ((tid & 31) == 0) red[tid >> 5] = m;
    __syncthreads();
    if (tid == 0) {
        float mm = red[0];
        for (int i = 1; i < 32; i++) mm = fmaxf(mm, red[i]);
        sM = mm;
    }
    __syncthreads();
    float M = sM;

    float z = 0.f;
    for (int s = tid; s < len; s += 1024) z += __expf(sc[s] - M);
#pragma unroll
    for (int o = 16; o; o >>= 1) z += __shfl_xor_sync(0xffffffffu, z, o);
    if ((tid & 31) == 0) red[tid >> 5] = z;
    __syncthreads();
    if (tid == 0) {
        float zz = 0.f;
        for (int i = 0; i < 32; i++) zz += red[i];
        sZ = zz;
    }
    __syncthreads();
    float inv = 1.f / sZ;
    for (int s = tid; s < len; s += 1024) d_energy[b * S_ + s] = __expf(sc[s] - M) * inv;
}

// ---------------- Kernel 4: context (fp32 enc for accuracy) ----------------
__global__ void k_zero(float* out) {
    int i = blockIdx.x * 256 + threadIdx.x;
    if (i < B_ * E2) out[i] = 0.f;
}

__global__ void k_context(const float* __restrict__ enc,
                          float* __restrict__ out) {
    int b = blockIdx.y;
    int len = d_len[b];
    int s0 = blockIdx.x * SCH;
    if (s0 >= len) return;
    int tid = threadIdx.x;  // 256 threads, each owns 4 consecutive e
    int ns = min(SCH, len - s0);

    __shared__ float es[SCH];
    if (tid < SCH) es[tid] = (tid < ns) ? d_energy[b * S_ + s0 + tid] : 0.f;
    __syncthreads();

    const float4* e4 = (const float4*)(enc + ((size_t)b * S_ + s0) * E2);
    float4 acc = make_float4(0.f, 0.f, 0.f, 0.f);
    for (int s = 0; s < ns; s++) {
        float ww = es[s];
        float4 v = e4[(size_t)s * (E2 / 4) + tid];
        acc.x += ww * v.x; acc.y += ww * v.y; acc.z += ww * v.z; acc.w += ww * v.w;
    }
    float* o = out + b * E2 + tid * 4;
    atomicAdd(o + 0, acc.x);
    atomicAdd(o + 1, acc.y);
    atomicAdd(o + 2, acc.z);
    atomicAdd(o + 3, acc.w);
}

// ---------------- launch ----------------
extern "C" void kernel_launch(void* const* d_in, const int* in_sizes, int n_in,
                              void* d_out, int out_size) {
    const float* enc     = (const float*)d_in[0];
    const float* hidden  = (const float*)d_in[1];
    const void*  lengths = d_in[2];
    const float* attn_w  = (const float*)d_in[3];
    const float* attn_b  = (const float*)d_in[4];
    const float* v_w     = (const float*)d_in[5];
    float* out = (float*)d_out;

    k_lengths<<<1, 32>>>(lengths);
    k_hidden<<<B_, DH>>>(hidden, attn_w, attn_b);
    k_conv_w<<<DH * E2 / 2 / 256, 256>>>(attn_w);
    k_conv_enc<<<dim3(S_ / 32, B_), 256>>>(enc);

    cudaFuncSetAttribute(k_scores, cudaFuncAttributeMaxDynamicSharedMemorySize, SMEM_TOTAL);
    k_scores<<<dim3(S_ / MTILE, E2 / NTILE / 2, B_), 512, SMEM_TOTAL>>>(v_w);

    k_softmax<<<B_, 1024>>>();

    k_zero<<<(B_ * E2 + 255) / 256, 256>>>(out);
    k_context<<<dim3(S_ / SCH, B_), 256>>>(enc, out);
}